// round 2
// baseline (speedup 1.0000x reference)
#include <cuda_runtime.h>
#include <stdint.h>

#define N_NODES 131072
#define LSQN    9
#define CDIM    128
#define HDIM    1024
#define NMOL    2048

// Scratch (static device globals — no runtime allocation).
__device__ float g_h1[(size_t)N_NODES * HDIM];   // 512 MB
__device__ float g_ne[N_NODES];

__device__ __forceinline__ float silu_f(float x) {
    return x / (1.0f + __expf(-x));
}

// ---------------------------------------------------------------------------
// Kernel 1: h1 = silu(x @ W1 + b1), x = node_embedding[:,0,:] (row stride 1152)
// 128x128 output tile per block, BK=16, 256 threads, 8x8 per-thread microtile.
// grid = (N/128, H/128)
// ---------------------------------------------------------------------------
__global__ __launch_bounds__(256) void k1_gemm_silu(
    const float* __restrict__ X,
    const float* __restrict__ W1,
    const float* __restrict__ b1)
{
    __shared__ float As[16][128];
    __shared__ float Bs[16][128];

    const int r0  = blockIdx.x * 128;
    const int n0  = blockIdx.y * 128;
    const int tid = threadIdx.x;
    const int tx  = tid & 15;       // 0..15 -> output cols tx*8..tx*8+7
    const int ty  = tid >> 4;       // 0..15 -> output rows ty*8..ty*8+7

    float acc[8][8];
#pragma unroll
    for (int i = 0; i < 8; i++)
#pragma unroll
        for (int j = 0; j < 8; j++) acc[i][j] = 0.0f;

    for (int kt = 0; kt < CDIM; kt += 16) {
#pragma unroll
        for (int l = 0; l < 2; l++) {
            int idx = tid + l * 256;
            // A tile: 128 rows x 16 k (strided source)
            int r  = idx >> 2;
            int kk = (idx & 3) << 2;
            float4 a = *(const float4*)(X + (size_t)(r0 + r) * (LSQN * CDIM) + kt + kk);
            As[kk + 0][r] = a.x; As[kk + 1][r] = a.y;
            As[kk + 2][r] = a.z; As[kk + 3][r] = a.w;
            // B tile: 16 k x 128 n
            int kb = idx >> 5;
            int nn = (idx & 31) << 2;
            float4 b = *(const float4*)(W1 + (size_t)(kt + kb) * HDIM + n0 + nn);
            *(float4*)&Bs[kb][nn] = b;
        }
        __syncthreads();

#pragma unroll
        for (int k = 0; k < 16; k++) {
            float am[8], bn[8];
            *(float4*)&am[0] = *(float4*)&As[k][ty * 8];
            *(float4*)&am[4] = *(float4*)&As[k][ty * 8 + 4];
            *(float4*)&bn[0] = *(float4*)&Bs[k][tx * 8];
            *(float4*)&bn[4] = *(float4*)&Bs[k][tx * 8 + 4];
#pragma unroll
            for (int i = 0; i < 8; i++)
#pragma unroll
                for (int j = 0; j < 8; j++)
                    acc[i][j] = fmaf(am[i], bn[j], acc[i][j]);
        }
        __syncthreads();
    }

    float bb[8];
#pragma unroll
    for (int j = 0; j < 8; j++) bb[j] = b1[n0 + tx * 8 + j];

#pragma unroll
    for (int i = 0; i < 8; i++) {
        float out[8];
#pragma unroll
        for (int j = 0; j < 8; j++) out[j] = silu_f(acc[i][j] + bb[j]);
        size_t base = (size_t)(r0 + ty * 8 + i) * HDIM + n0 + tx * 8;
        *(float4*)(g_h1 + base)     = *(float4*)&out[0];
        *(float4*)(g_h1 + base + 4) = *(float4*)&out[4];
    }
}

// ---------------------------------------------------------------------------
// Kernel 2: fused  h2 = silu(h1 @ W2 + b2);  ne = h2 @ W3 + b3
// One block owns 128 rows and loops over all 8 n-tiles -> no atomics,
// fully deterministic. grid = N/128
// ---------------------------------------------------------------------------
__global__ __launch_bounds__(256) void k2_gemm_fused(
    const float* __restrict__ W2,
    const float* __restrict__ b2,
    const float* __restrict__ W3,
    const float* __restrict__ b3)
{
    __shared__ float As[16][128];
    __shared__ float Bs[16][128];
    __shared__ float red[128][17];   // padded to kill bank conflicts

    const int r0  = blockIdx.x * 128;
    const int tid = threadIdx.x;
    const int tx  = tid & 15;
    const int ty  = tid >> 4;

    float e8[8];
#pragma unroll
    for (int i = 0; i < 8; i++) e8[i] = 0.0f;

    for (int nt = 0; nt < HDIM; nt += 128) {
        float acc[8][8];
#pragma unroll
        for (int i = 0; i < 8; i++)
#pragma unroll
            for (int j = 0; j < 8; j++) acc[i][j] = 0.0f;

        for (int kt = 0; kt < HDIM; kt += 16) {
#pragma unroll
            for (int l = 0; l < 2; l++) {
                int idx = tid + l * 256;
                int r  = idx >> 2;
                int kk = (idx & 3) << 2;
                float4 a = *(const float4*)(g_h1 + (size_t)(r0 + r) * HDIM + kt + kk);
                As[kk + 0][r] = a.x; As[kk + 1][r] = a.y;
                As[kk + 2][r] = a.z; As[kk + 3][r] = a.w;
                int kb = idx >> 5;
                int nn = (idx & 31) << 2;
                float4 b = *(const float4*)(W2 + (size_t)(kt + kb) * HDIM + nt + nn);
                *(float4*)&Bs[kb][nn] = b;
            }
            __syncthreads();

#pragma unroll
            for (int k = 0; k < 16; k++) {
                float am[8], bn[8];
                *(float4*)&am[0] = *(float4*)&As[k][ty * 8];
                *(float4*)&am[4] = *(float4*)&As[k][ty * 8 + 4];
                *(float4*)&bn[0] = *(float4*)&Bs[k][tx * 8];
                *(float4*)&bn[4] = *(float4*)&Bs[k][tx * 8 + 4];
#pragma unroll
                for (int i = 0; i < 8; i++)
#pragma unroll
                    for (int j = 0; j < 8; j++)
                        acc[i][j] = fmaf(am[i], bn[j], acc[i][j]);
            }
            __syncthreads();
        }

        // epilogue for this n-tile: silu + dot with W3 slice
        float bb[8], w3r[8];
#pragma unroll
        for (int j = 0; j < 8; j++) {
            bb[j]  = b2[nt + tx * 8 + j];
            w3r[j] = W3[nt + tx * 8 + j];     // W3 is (H,1) contiguous
        }
#pragma unroll
        for (int i = 0; i < 8; i++) {
            float s = 0.0f;
#pragma unroll
            for (int j = 0; j < 8; j++)
                s = fmaf(silu_f(acc[i][j] + bb[j]), w3r[j], s);
            e8[i] += s;
        }
    }

    // reduce partial energies across the 16 tx threads sharing each row
#pragma unroll
    for (int i = 0; i < 8; i++) red[ty * 8 + i][tx] = e8[i];
    __syncthreads();

    if (tid < 128) {
        float s = 0.0f;
#pragma unroll
        for (int t = 0; t < 16; t++) s += red[tid][t];
        g_ne[r0 + tid] = s + b3[0];
    }
}

// ---------------------------------------------------------------------------
// Kernel 3: deterministic segment sum over the SORTED batch array.
//
// Dtype robustness: the reference declares batch as int64, but JAX with
// default config silently produces int32. We therefore treat the buffer as
// raw 32-bit words (in-bounds for BOTH dtypes, since we never touch word
// index >= N) and detect the dtype on device: word[N-1] is the max batch id
// (>0) for int32 data, but a zero high-word for int64 data.
//   int64: element i = word[2*i]  (values < 2^31, little-endian)
//   int32: element i = word[i]
// One warp per molecule: binary search the contiguous range, warp-reduce.
// ---------------------------------------------------------------------------
__global__ __launch_bounds__(256) void k3_segsum(
    const uint32_t* __restrict__ bw,
    float* __restrict__ out)
{
    int warp = (blockIdx.x * blockDim.x + threadIdx.x) >> 5;
    int lane = threadIdx.x & 31;
    if (warp >= NMOL) return;

    int lo = 0, hi = 0;
    if (lane == 0) {
        const bool is64 = (bw[N_NODES - 1] == 0u);   // high word of elem N/2-1 if int64
        const uint32_t m = (uint32_t)warp;
        int a = 0, b = N_NODES;
        while (a < b) {
            int mid = (a + b) >> 1;
            uint32_t v = is64 ? bw[2 * (size_t)mid] : bw[mid];
            if (v < m) a = mid + 1; else b = mid;
        }
        lo = a;
        a = lo; b = N_NODES;
        while (a < b) {
            int mid = (a + b) >> 1;
            uint32_t v = is64 ? bw[2 * (size_t)mid] : bw[mid];
            if (v <= m) a = mid + 1; else b = mid;
        }
        hi = a;
    }
    lo = __shfl_sync(0xffffffffu, lo, 0);
    hi = __shfl_sync(0xffffffffu, hi, 0);

    float s = 0.0f;
    for (int i = lo + lane; i < hi; i += 32) s += g_ne[i];
#pragma unroll
    for (int o = 16; o > 0; o >>= 1) s += __shfl_down_sync(0xffffffffu, s, o);
    if (lane == 0) out[warp] = s;
}

// ---------------------------------------------------------------------------
extern "C" void kernel_launch(void* const* d_in, const int* in_sizes, int n_in,
                              void* d_out, int out_size)
{
    const float*    X     = (const float*)d_in[0];   // node_embedding (N,9,128)
    const float*    W1    = (const float*)d_in[1];   // (128,1024)
    const float*    b1    = (const float*)d_in[2];   // (1024,)
    const float*    W2    = (const float*)d_in[3];   // (1024,1024)
    const float*    b2    = (const float*)d_in[4];   // (1024,)
    const float*    W3    = (const float*)d_in[5];   // (1024,1)
    const float*    b3    = (const float*)d_in[6];   // (1,)
    const uint32_t* batchw= (const uint32_t*)d_in[7];// (N,) int32 OR int64 (detected on device)
    // d_in[8] = natoms: unused by the reference computation
    float* out = (float*)d_out;

    dim3 g1(N_NODES / 128, HDIM / 128);
    k1_gemm_silu<<<g1, 256>>>(X, W1, b1);
    k2_gemm_fused<<<N_NODES / 128, 256>>>(W2, b2, W3, b3);
    k3_segsum<<<(NMOL * 32) / 256, 256>>>(batchw, out);
}

// round 4
// speedup vs baseline: 2.6135x; 2.6135x over previous
#include <cuda_runtime.h>
#include <cuda_bf16.h>
#include <stdint.h>

#define N_NODES 131072
#define LSQN    9
#define CDIM    128
#define HDIM    1024
#define NMOL    2048

// ---------------- device scratch (static, no runtime allocation) -----------
__device__ __nv_bfloat16 g_xh[(size_t)N_NODES * CDIM];
__device__ __nv_bfloat16 g_xl[(size_t)N_NODES * CDIM];
__device__ __nv_bfloat16 g_h1h[(size_t)N_NODES * HDIM];
__device__ __nv_bfloat16 g_h1l[(size_t)N_NODES * HDIM];
__device__ __nv_bfloat16 g_w1h[HDIM * CDIM];              // W1^T [n][k]
__device__ __nv_bfloat16 g_w1l[HDIM * CDIM];
__device__ __nv_bfloat16 g_w2h[(size_t)HDIM * HDIM];      // W2^T [n][k]
__device__ __nv_bfloat16 g_w2l[(size_t)HDIM * HDIM];
__device__ float         g_nep[8][N_NODES];               // per-ncol partial energies

// ---------------- helpers ---------------------------------------------------
__device__ __forceinline__ float silu_f(float x) { return x / (1.0f + __expf(-x)); }

__device__ __forceinline__ uint32_t pack2(float a, float b) {
    __nv_bfloat162 p = __floats2bfloat162_rn(a, b);
    return *(uint32_t*)&p;
}
__device__ __forceinline__ void split2(float a, float b, uint32_t& hi, uint32_t& lo) {
    __nv_bfloat16 ha = __float2bfloat16(a), hb = __float2bfloat16(b);
    hi = ((uint32_t)__bfloat16_as_ushort(hb) << 16) | __bfloat16_as_ushort(ha);
    lo = pack2(a - __bfloat162float(ha), b - __bfloat162float(hb));
}

__device__ __forceinline__ void ldsm4(uint32_t r[4], uint32_t a) {
    asm volatile("ldmatrix.sync.aligned.m8n8.x4.shared.b16 {%0,%1,%2,%3}, [%4];"
                 : "=r"(r[0]), "=r"(r[1]), "=r"(r[2]), "=r"(r[3]) : "r"(a));
}
__device__ __forceinline__ void mma16816(float* c, const uint32_t a[4],
                                         uint32_t b0, uint32_t b1) {
    asm volatile(
        "mma.sync.aligned.m16n8k16.row.col.f32.bf16.bf16.f32 "
        "{%0,%1,%2,%3},{%4,%5,%6,%7},{%8,%9},{%0,%1,%2,%3};"
        : "+f"(c[0]), "+f"(c[1]), "+f"(c[2]), "+f"(c[3])
        : "r"(a[0]), "r"(a[1]), "r"(a[2]), "r"(a[3]), "r"(b0), "r"(b1));
}
#define CP16(dst, src) asm volatile("cp.async.cg.shared.global [%0], [%1], 16;" :: "r"(dst), "l"(src) : "memory")
#define CP_COMMIT()    asm volatile("cp.async.commit_group;" ::: "memory")
#define CP_WAIT1()     asm volatile("cp.async.wait_group 1;" ::: "memory")
#define CP_WAIT0()     asm volatile("cp.async.wait_group 0;" ::: "memory")

// SMEM stage layout: [A hi |A lo |B hi |B lo], each plane 128 rows x 80B
#define ROWB  80
#define PLANE (128 * ROWB)          // 10240
#define STG   (4 * PLANE)           // 40960
#define SMEMB (2 * STG)             // 81920

// ---------------- prep kernels ----------------------------------------------
__global__ __launch_bounds__(256) void prep_x(const float* __restrict__ X) {
    int i = blockIdx.x * 256 + threadIdx.x;          // one float4 each
    int r = i >> 5, k = (i & 31) << 2;
    float4 f = *(const float4*)(X + (size_t)r * (LSQN * CDIM) + k);
    uint32_t h0, l0, h1, l1;
    split2(f.x, f.y, h0, l0);
    split2(f.z, f.w, h1, l1);
    size_t o = (size_t)r * CDIM + k;
    *(uint2*)(g_xh + o) = make_uint2(h0, h1);
    *(uint2*)(g_xl + o) = make_uint2(l0, l1);
}

__global__ __launch_bounds__(256) void prep_w(const float* __restrict__ W1,
                                              const float* __restrict__ W2) {
    int i = blockIdx.x * 256 + threadIdx.x;
    if (i < HDIM * CDIM) {                            // W1t[n][k] = W1[k][n]
        int n = i >> 7, k = i & 127;
        float v = W1[(size_t)k * HDIM + n];
        __nv_bfloat16 h = __float2bfloat16(v);
        g_w1h[i] = h;
        g_w1l[i] = __float2bfloat16(v - __bfloat162float(h));
    }
    if (i < HDIM * HDIM) {                            // W2t[n][k] = W2[k][n]
        int n = i >> 10, k = i & 1023;
        float v = W2[(size_t)k * HDIM + n];
        __nv_bfloat16 h = __float2bfloat16(v);
        g_w2h[i] = h;
        g_w2l[i] = __float2bfloat16(v - __bfloat162float(h));
    }
}

// ---------------- main GEMM: 128x128 block, 4 warps, warp tile 64x64 --------
// LAYER 1: h1 = silu(x @ W1 + b1)           -> g_h1h/g_h1l
// LAYER 2: e  = silu(h1 @ W2 + b2) . W3     -> g_nep[ncol][row]
template<int LAYER>
__global__ __launch_bounds__(128, 2) void gemm_mma(
    const float* __restrict__ bias,
    const float* __restrict__ W3,
    const float* __restrict__ b3)
{
    extern __shared__ char smem[];
    const uint32_t sb  = (uint32_t)__cvta_generic_to_shared(smem);
    const int tid  = threadIdx.x;
    const int L    = tid & 31;
    const int wid  = tid >> 5;
    const int wm   = wid >> 1;          // 0..1
    const int wn   = wid & 1;           // 0..1
    const int r0   = blockIdx.y * 128;
    const int n0   = blockIdx.x * 128;

    const __nv_bfloat16 *Ah, *Al, *Bh, *Bl;
    int lda, ldb, NK;
    if (LAYER == 1) { Ah = g_xh;  Al = g_xl;  Bh = g_w1h; Bl = g_w1l; lda = 128;  ldb = 128;  NK = 4;  }
    else            { Ah = g_h1h; Al = g_h1l; Bh = g_w2h; Bl = g_w2l; lda = 1024; ldb = 1024; NK = 32; }

    float acc[4][8][4];
#pragma unroll
    for (int a = 0; a < 4; a++)
#pragma unroll
        for (int b = 0; b < 8; b++)
#pragma unroll
            for (int c = 0; c < 4; c++) acc[a][b][c] = 0.0f;

    // per-lane ldmatrix offsets (80B rows, conflict-free)
    const uint32_t a_off = (uint32_t)((wm * 64 + (L & 15)) * ROWB + (L >> 4) * 16);
    const uint32_t b_off = (uint32_t)((wn * 64 + ((L >> 4) & 1) * 8 + (L & 7)) * ROWB
                                      + ((L >> 3) & 1) * 16);

    // stage loader: 2048 16B chunks / 128 threads = 16 each
    auto load_stage = [&](int kt, int s) {
#pragma unroll
        for (int i0 = 0; i0 < 16; i0++) {
            int i  = i0 * 128 + tid;
            int ab = i >> 10, pl = (i >> 9) & 1, r = (i >> 2) & 127, c = i & 3;
            const __nv_bfloat16* src = ab
                ? ((pl ? Bl : Bh) + (size_t)(n0 + r) * ldb + kt * 32 + c * 8)
                : ((pl ? Al : Ah) + (size_t)(r0 + r) * lda + kt * 32 + c * 8);
            uint32_t dst = sb + s * STG + ab * (2 * PLANE) + pl * PLANE + r * ROWB + c * 16;
            CP16(dst, src);
        }
        CP_COMMIT();
    };

    load_stage(0, 0);
    for (int kt = 0; kt < NK; kt++) {
        if (kt + 1 < NK) { load_stage(kt + 1, (kt + 1) & 1); CP_WAIT1(); }
        else             { CP_WAIT0(); }
        __syncthreads();
        const uint32_t base = sb + (kt & 1) * STG;

#pragma unroll
        for (int kk = 0; kk < 2; kk++) {
            uint32_t ah[4][4], bh[4][4], x[4][4];
#pragma unroll
            for (int am = 0; am < 4; am++)
                ldsm4(ah[am], base + a_off + am * 16 * ROWB + kk * 32);
#pragma unroll
            for (int jj = 0; jj < 4; jj++)
                ldsm4(bh[jj], base + 2 * PLANE + b_off + jj * 16 * ROWB + kk * 32);
#pragma unroll
            for (int am = 0; am < 4; am++)
#pragma unroll
                for (int jj = 0; jj < 4; jj++) {
                    mma16816(acc[am][2 * jj],     ah[am], bh[jj][0], bh[jj][1]);
                    mma16816(acc[am][2 * jj + 1], ah[am], bh[jj][2], bh[jj][3]);
                }
            // Ah x Bl
#pragma unroll
            for (int jj = 0; jj < 4; jj++)
                ldsm4(x[jj], base + 3 * PLANE + b_off + jj * 16 * ROWB + kk * 32);
#pragma unroll
            for (int am = 0; am < 4; am++)
#pragma unroll
                for (int jj = 0; jj < 4; jj++) {
                    mma16816(acc[am][2 * jj],     ah[am], x[jj][0], x[jj][1]);
                    mma16816(acc[am][2 * jj + 1], ah[am], x[jj][2], x[jj][3]);
                }
            // Al x Bh
#pragma unroll
            for (int am = 0; am < 4; am++)
                ldsm4(x[am], base + PLANE + a_off + am * 16 * ROWB + kk * 32);
#pragma unroll
            for (int am = 0; am < 4; am++)
#pragma unroll
                for (int jj = 0; jj < 4; jj++) {
                    mma16816(acc[am][2 * jj],     x[am], bh[jj][0], bh[jj][1]);
                    mma16816(acc[am][2 * jj + 1], x[am], bh[jj][2], bh[jj][3]);
                }
        }
        __syncthreads();
    }

    const int g   = L >> 2;
    const int tig = L & 3;

    if (LAYER == 1) {
        // silu + hi/lo split -> h1 planes
#pragma unroll
        for (int am = 0; am < 4; am++) {
            int rm = r0 + wm * 64 + am * 16 + g;
#pragma unroll
            for (int an = 0; an < 8; an++) {
                int n = n0 + wn * 64 + an * 8 + 2 * tig;
                float2 bb = *(const float2*)(bias + n);
                uint32_t hi, lo;
                split2(silu_f(acc[am][an][0] + bb.x), silu_f(acc[am][an][1] + bb.y), hi, lo);
                *(uint32_t*)(g_h1h + (size_t)rm * HDIM + n) = hi;
                *(uint32_t*)(g_h1l + (size_t)rm * HDIM + n) = lo;
                split2(silu_f(acc[am][an][2] + bb.x), silu_f(acc[am][an][3] + bb.y), hi, lo);
                *(uint32_t*)(g_h1h + (size_t)(rm + 8) * HDIM + n) = hi;
                *(uint32_t*)(g_h1l + (size_t)(rm + 8) * HDIM + n) = lo;
            }
        }
    } else {
        // silu + dot(W3), quad reduce, block reduce -> g_nep
        float* red = (float*)smem;       // 256 floats, buffers dead
#pragma unroll
        for (int am = 0; am < 4; am++) {
            float sA = 0.0f, sB = 0.0f;
#pragma unroll
            for (int an = 0; an < 8; an++) {
                int n = n0 + wn * 64 + an * 8 + 2 * tig;
                float2 bb = *(const float2*)(bias + n);
                float2 ww = *(const float2*)(W3 + n);
                sA += silu_f(acc[am][an][0] + bb.x) * ww.x
                    + silu_f(acc[am][an][1] + bb.y) * ww.y;
                sB += silu_f(acc[am][an][2] + bb.x) * ww.x
                    + silu_f(acc[am][an][3] + bb.y) * ww.y;
            }
#pragma unroll
            for (int o = 1; o <= 2; o <<= 1) {
                sA += __shfl_xor_sync(0xffffffffu, sA, o);
                sB += __shfl_xor_sync(0xffffffffu, sB, o);
            }
            if (tig == 0) {
                red[wn * 128 + wm * 64 + am * 16 + g]     = sA;
                red[wn * 128 + wm * 64 + am * 16 + g + 8] = sB;
            }
        }
        __syncthreads();
        if (tid < 128) {
            float v = red[tid] + red[128 + tid];
            if (blockIdx.x == 0) v += b3[0];
            g_nep[blockIdx.x][r0 + tid] = v;
        }
    }
}

// ---------------- k3: deterministic segment sum over sorted batch ----------
__global__ __launch_bounds__(256) void k3_segsum(const uint32_t* __restrict__ bw,
                                                 float* __restrict__ out) {
    int warp = (blockIdx.x * blockDim.x + threadIdx.x) >> 5;
    int lane = threadIdx.x & 31;
    if (warp >= NMOL) return;
    int lo = 0, hi = 0;
    if (lane == 0) {
        const bool is64 = (bw[N_NODES - 1] == 0u);   // int64 high word if so
        const uint32_t m = (uint32_t)warp;
        int a = 0, b = N_NODES;
        while (a < b) { int mid = (a + b) >> 1;
            uint32_t v = is64 ? bw[2 * (size_t)mid] : bw[mid];
            if (v < m) a = mid + 1; else b = mid; }
        lo = a; a = lo; b = N_NODES;
        while (a < b) { int mid = (a + b) >> 1;
            uint32_t v = is64 ? bw[2 * (size_t)mid] : bw[mid];
            if (v <= m) a = mid + 1; else b = mid; }
        hi = a;
    }
    lo = __shfl_sync(0xffffffffu, lo, 0);
    hi = __shfl_sync(0xffffffffu, hi, 0);
    float s = 0.0f;
    for (int i = lo + lane; i < hi; i += 32) {
        float t = 0.0f;
#pragma unroll
        for (int q = 0; q < 8; q++) t += g_nep[q][i];
        s += t;
    }
#pragma unroll
    for (int o = 16; o > 0; o >>= 1) s += __shfl_down_sync(0xffffffffu, s, o);
    if (lane == 0) out[warp] = s;
}

// ---------------------------------------------------------------------------
extern "C" void kernel_launch(void* const* d_in, const int* in_sizes, int n_in,
                              void* d_out, int out_size)
{
    const float*    X      = (const float*)d_in[0];
    const float*    W1     = (const float*)d_in[1];
    const float*    b1     = (const float*)d_in[2];
    const float*    W2     = (const float*)d_in[3];
    const float*    b2     = (const float*)d_in[4];
    const float*    W3     = (const float*)d_in[5];
    const float*    b3     = (const float*)d_in[6];
    const uint32_t* batchw = (const uint32_t*)d_in[7];
    float* out = (float*)d_out;

    static bool attr = false;
    if (!attr) {
        cudaFuncSetAttribute(gemm_mma<1>, cudaFuncAttributeMaxDynamicSharedMemorySize, SMEMB);
        cudaFuncSetAttribute(gemm_mma<2>, cudaFuncAttributeMaxDynamicSharedMemorySize, SMEMB);
        attr = true;
    }

    prep_x<<<(N_NODES * CDIM / 4) / 256, 256>>>(X);
    prep_w<<<(HDIM * HDIM) / 256, 256>>>(W1, W2);
    dim3 grid(HDIM / 128, N_NODES / 128);
    gemm_mma<1><<<grid, 128, SMEMB>>>(b1, nullptr, nullptr);
    gemm_mma<2><<<grid, 128, SMEMB>>>(b2, W3, b3);
    k3_segsum<<<(NMOL * 32) / 256, 256>>>(batchw, out);
}